// round 1
// baseline (speedup 1.0000x reference)
#include <cuda_runtime.h>
#include <math.h>

#define NN 2048
#define CC 384
#define HH 16
#define DD 24

// Scratch (allocation-free rule: __device__ globals)
__device__ float g_xn[NN*CC];
__device__ float g_q[NN*CC];      // [H][N][D], pre-scaled by D^-0.5
__device__ float g_k[NN*CC];      // [H][N][D]
__device__ float g_v[NN*CC];      // [H][N][D]
__device__ float g_gate[NN*CC];   // sigmoid(xn @ wg.T), [N][C]
__device__ float g_gated[NN*CC];  // wa * gate, [N][C]
__device__ float g_biask[NN];     // 1e9*(mask-1)

// ---------------------------------------------------------------------------
// LayerNorm over C=384 per row; also precompute additive key bias.
// ---------------------------------------------------------------------------
__global__ __launch_bounds__(128) void ln_kernel(
    const float* __restrict__ x, const float* __restrict__ mask,
    const float* __restrict__ ln_w, const float* __restrict__ ln_b) {
  int row = blockIdx.x, tid = threadIdx.x;
  const float* xr = x + row*CC;
  float v[3]; float s = 0.f;
  #pragma unroll
  for (int i=0;i<3;i++){ v[i]=xr[tid+128*i]; s+=v[i]; }
  __shared__ float red[4];
  #pragma unroll
  for (int o=16;o;o>>=1) s += __shfl_xor_sync(~0u,s,o);
  if ((tid&31)==0) red[tid>>5]=s;
  __syncthreads();
  float mu = (red[0]+red[1]+red[2]+red[3])*(1.f/CC);
  __syncthreads();
  float sq=0.f;
  #pragma unroll
  for (int i=0;i<3;i++){ float d=v[i]-mu; sq+=d*d; }
  #pragma unroll
  for (int o=16;o;o>>=1) sq += __shfl_xor_sync(~0u,sq,o);
  if ((tid&31)==0) red[tid>>5]=sq;
  __syncthreads();
  float var = (red[0]+red[1]+red[2]+red[3])*(1.f/CC);
  float rs = rsqrtf(var + 1e-5f);
  #pragma unroll
  for (int i=0;i<3;i++){
    int c = tid+128*i;
    g_xn[row*CC+c] = (v[i]-mu)*rs*ln_w[c] + ln_b[c];
  }
  if (tid==0) g_biask[row] = 1e9f*(mask[row]-1.f);
}

// ---------------------------------------------------------------------------
// 64x64x(K=384) fp32 tiled GEMM:  out[n][c] = sum_k A[n][k]*B[c][k]
// Both operands K-contiguous (y = x @ W.T).  smem stored [k][m] transposed
// so compute-side float4 reads are conflict-free.
// ---------------------------------------------------------------------------
__device__ __forceinline__ void gemm64(const float* __restrict__ A,
                                       const float* __restrict__ B,
                                       int n0, int c0, float acc[4][4]) {
  __shared__ __align__(16) float As[32][68];
  __shared__ __align__(16) float Bs[32][68];
  int tid = threadIdx.x;
  int tx = tid & 15, ty = tid >> 4;
  for (int kt=0; kt<12; kt++){
    int k0 = kt*32;
    #pragma unroll
    for (int i=0;i<2;i++){
      int f = tid + i*256;
      int r = f>>3, k4 = f&7;
      float4 a = *(const float4*)&A[(n0+r)*CC + k0 + k4*4];
      As[k4*4+0][r]=a.x; As[k4*4+1][r]=a.y; As[k4*4+2][r]=a.z; As[k4*4+3][r]=a.w;
      float4 b = *(const float4*)&B[(c0+r)*CC + k0 + k4*4];
      Bs[k4*4+0][r]=b.x; Bs[k4*4+1][r]=b.y; Bs[k4*4+2][r]=b.z; Bs[k4*4+3][r]=b.w;
    }
    __syncthreads();
    #pragma unroll
    for (int kk=0;kk<32;kk++){
      float4 a = *(const float4*)&As[kk][ty*4];
      float4 b = *(const float4*)&Bs[kk][tx*4];
      float av[4]={a.x,a.y,a.z,a.w}, bv[4]={b.x,b.y,b.z,b.w};
      #pragma unroll
      for (int r=0;r<4;r++)
        #pragma unroll
        for (int c=0;c<4;c++) acc[r][c] += av[r]*bv[c];
    }
    __syncthreads();
  }
}

// ---------------------------------------------------------------------------
// All four projections in one kernel (blockIdx.z selects q/k/v/g).
// ---------------------------------------------------------------------------
__global__ __launch_bounds__(256) void proj_kernel(
    const float* __restrict__ wq, const float* __restrict__ bq,
    const float* __restrict__ wk, const float* __restrict__ wv,
    const float* __restrict__ wg) {
  int proj = blockIdx.z;
  const float* W = (proj==0)?wq:(proj==1)?wk:(proj==2)?wv:wg;
  int c0 = blockIdx.x*64, n0 = blockIdx.y*64;
  float acc[4][4] = {};
  gemm64(g_xn, W, n0, c0, acc);
  int tx = threadIdx.x & 15, ty = threadIdx.x >> 4;
  #pragma unroll
  for (int r=0;r<4;r++){
    int row = n0 + ty*4 + r;
    #pragma unroll
    for (int c=0;c<4;c++){
      int col = c0 + tx*4 + c;
      float val = acc[r][c];
      if (proj==0){
        val = (val + bq[col]) * 0.2041241452f;   // D^-0.5
        g_q[(col/DD)*NN*DD + row*DD + (col%DD)] = val;
      } else if (proj==1){
        g_k[(col/DD)*NN*DD + row*DD + (col%DD)] = val;
      } else if (proj==2){
        g_v[(col/DD)*NN*DD + row*DD + (col%DD)] = val;
      } else {
        g_gate[row*CC+col] = 1.f/(1.f+__expf(-val));
      }
    }
  }
}

// ---------------------------------------------------------------------------
// Flash-attention per (head, 64-query tile).  Streams 64-key tiles:
// stage pair_logits+bias into smem, add QK^T, online softmax, PV accumulate.
// Thread (qi = tid>>2, l4 = tid&3): owns 16 score columns (kj = l4+4j,
// bank-conflict-free) and 6 output channels (d = l4*6..+5).
// Epilogue fuses the sigmoid-gate multiply.
// ---------------------------------------------------------------------------
__global__ __launch_bounds__(256) void attn_kernel(const float* __restrict__ pair) {
  int h = blockIdx.y, q0 = blockIdx.x*64;
  __shared__ float k_s[64][24];
  __shared__ float v_s[64][24];
  __shared__ float s_s[64][68];   // stride 68 -> bank = 4*qi+l4, conflict-free
  int tid = threadIdx.x;
  int qi = tid>>2, l4 = tid&3;

  float qreg[24];
  {
    const float* qp = &g_q[h*NN*DD + (q0+qi)*DD];
    #pragma unroll
    for (int d=0;d<24;d++) qreg[d]=qp[d];
  }
  float m = -1e30f, l = 0.f;
  float acc[6] = {0.f,0.f,0.f,0.f,0.f,0.f};
  const float* pbase = pair + (size_t)h*NN*NN;

  for (int t=0;t<32;t++){
    int k0 = t*64;
    // stage K/V tile (coalesced) and pair+bias tile
    for (int idx=tid; idx<64*24; idx+=256){
      int r = idx/24, d = idx - r*24;
      k_s[r][d] = g_k[h*NN*DD + (k0+r)*DD + d];
      v_s[r][d] = g_v[h*NN*DD + (k0+r)*DD + d];
    }
    for (int idx=tid; idx<4096; idx+=256){
      int r = idx>>6, c = idx&63;
      s_s[r][c] = pbase[(size_t)(q0+r)*NN + k0 + c] + g_biask[k0+c];
    }
    __syncthreads();

    // scores: s = pair + bias + q.k
    float sc[16]; float rowmax = -1e30f;
    #pragma unroll
    for (int j=0;j<16;j++){
      int kj = l4 + 4*j;
      float s = s_s[qi][kj];
      const float2* kp = (const float2*)&k_s[kj][0];
      #pragma unroll
      for (int d2=0; d2<12; d2++){
        float2 kv = kp[d2];
        s += qreg[2*d2]*kv.x + qreg[2*d2+1]*kv.y;
      }
      sc[j]=s; rowmax = fmaxf(rowmax, s);
    }
    // row reductions across the 4 lanes owning this row
    rowmax = fmaxf(rowmax, __shfl_xor_sync(~0u, rowmax, 1));
    rowmax = fmaxf(rowmax, __shfl_xor_sync(~0u, rowmax, 2));
    float mnew = fmaxf(m, rowmax);
    float lsum = 0.f;
    #pragma unroll
    for (int j=0;j<16;j++){
      float p = __expf(sc[j]-mnew);
      s_s[qi][l4+4*j] = p;      // overwrite own entries with p
      lsum += p;
    }
    lsum += __shfl_xor_sync(~0u,lsum,1);
    lsum += __shfl_xor_sync(~0u,lsum,2);
    float alpha = __expf(m - mnew);
    l = l*alpha + lsum;
    m = mnew;
    #pragma unroll
    for (int dd=0;dd<6;dd++) acc[dd]*=alpha;
    __syncthreads();   // all p values visible

    // PV: acc[d] += p[qi][kj] * v[kj][d]
    int d0 = l4*6;
    #pragma unroll 8
    for (int kj=0;kj<64;kj++){
      float p = s_s[qi][kj];
      const float2* vp = (const float2*)&v_s[kj][d0];
      float2 v0=vp[0], v1=vp[1], v2=vp[2];
      acc[0]+=p*v0.x; acc[1]+=p*v0.y; acc[2]+=p*v1.x;
      acc[3]+=p*v1.y; acc[4]+=p*v2.x; acc[5]+=p*v2.y;
    }
    __syncthreads();   // before next tile overwrites smem
  }

  float inv = 1.f/l;
  int n = q0+qi;
  #pragma unroll
  for (int dd=0;dd<6;dd++){
    int c = h*DD + l4*6 + dd;
    g_gated[n*CC + c] = acc[dd]*inv * g_gate[n*CC + c];
  }
}

// ---------------------------------------------------------------------------
// Output projection: out = gated @ wo.T
// ---------------------------------------------------------------------------
__global__ __launch_bounds__(256) void out_kernel(const float* __restrict__ wo,
                                                  float* __restrict__ out) {
  int c0 = blockIdx.x*64, n0 = blockIdx.y*64;
  float acc[4][4] = {};
  gemm64(g_gated, wo, n0, c0, acc);
  int tx = threadIdx.x & 15, ty = threadIdx.x >> 4;
  #pragma unroll
  for (int r=0;r<4;r++)
    #pragma unroll
    for (int c=0;c<4;c++)
      out[(n0+ty*4+r)*CC + c0+tx*4+c] = acc[r][c];
}

// ---------------------------------------------------------------------------
extern "C" void kernel_launch(void* const* d_in, const int* in_sizes, int n_in,
                              void* d_out, int out_size) {
  const float* x    = (const float*)d_in[0];
  const float* mask = (const float*)d_in[1];
  const float* pair = (const float*)d_in[2];
  const float* ln_w = (const float*)d_in[3];
  const float* ln_b = (const float*)d_in[4];
  const float* wq   = (const float*)d_in[5];
  const float* bq   = (const float*)d_in[6];
  const float* wk   = (const float*)d_in[7];
  const float* wv   = (const float*)d_in[8];
  const float* wg   = (const float*)d_in[9];
  const float* wo   = (const float*)d_in[10];
  float* out = (float*)d_out;

  ln_kernel<<<NN,128>>>(x,mask,ln_w,ln_b);
  proj_kernel<<<dim3(6,32,4),256>>>(wq,bq,wk,wv,wg);
  attn_kernel<<<dim3(32,16),256>>>(pair);
  out_kernel<<<dim3(6,32),256>>>(wo,out);
}

// round 3
// speedup vs baseline: 2.5860x; 2.5860x over previous
#include <cuda_runtime.h>
#include <math.h>

#define NN 2048
#define CC 384
#define HH 16
#define DD 24
#define L2E 1.44269504088896340736f

// Scratch (allocation-free rule: __device__ globals)
__device__ float g_xn[NN*CC];
__device__ float g_q[NN*CC];      // [H][N][D], pre-scaled by D^-0.5 * log2e
__device__ float g_k[NN*CC];      // [H][N][D]
__device__ float g_v[NN*CC];      // [H][N][D]
__device__ float g_gate[NN*CC];   // sigmoid(xn @ wg.T), [N][C]
__device__ float g_gated[NN*CC];  // wa * gate, [N][C]
__device__ float g_biask[NN];     // 1e9*(mask-1)*log2e

// ---------------------------------------------------------------------------
__device__ __forceinline__ unsigned cvt_tf32(float x){
  unsigned r; asm("cvt.rna.tf32.f32 %0, %1;" : "=r"(r) : "f"(x)); return r;
}
__device__ __forceinline__ void mma_tf32(float c[4], const unsigned a[4],
                                         unsigned b0, unsigned b1){
  asm volatile("mma.sync.aligned.m16n8k8.row.col.f32.tf32.tf32.f32 "
    "{%0,%1,%2,%3}, {%4,%5,%6,%7}, {%8,%9}, {%0,%1,%2,%3};"
    : "+f"(c[0]),"+f"(c[1]),"+f"(c[2]),"+f"(c[3])
    : "r"(a[0]),"r"(a[1]),"r"(a[2]),"r"(a[3]), "r"(b0),"r"(b1));
}

// ---------------------------------------------------------------------------
// LayerNorm over C=384 per row; also precompute additive key bias (log2 dom).
// ---------------------------------------------------------------------------
__global__ __launch_bounds__(128) void ln_kernel(
    const float* __restrict__ x, const float* __restrict__ mask,
    const float* __restrict__ ln_w, const float* __restrict__ ln_b) {
  int row = blockIdx.x, tid = threadIdx.x;
  const float* xr = x + row*CC;
  float v[3]; float s = 0.f;
  #pragma unroll
  for (int i=0;i<3;i++){ v[i]=xr[tid+128*i]; s+=v[i]; }
  __shared__ float red[4];
  #pragma unroll
  for (int o=16;o;o>>=1) s += __shfl_xor_sync(~0u,s,o);
  if ((tid&31)==0) red[tid>>5]=s;
  __syncthreads();
  float mu = (red[0]+red[1]+red[2]+red[3])*(1.f/CC);
  __syncthreads();
  float sq=0.f;
  #pragma unroll
  for (int i=0;i<3;i++){ float d=v[i]-mu; sq+=d*d; }
  #pragma unroll
  for (int o=16;o;o>>=1) sq += __shfl_xor_sync(~0u,sq,o);
  if ((tid&31)==0) red[tid>>5]=sq;
  __syncthreads();
  float var = (red[0]+red[1]+red[2]+red[3])*(1.f/CC);
  float rs = rsqrtf(var + 1e-5f);
  #pragma unroll
  for (int i=0;i<3;i++){
    int c = tid+128*i;
    g_xn[row*CC+c] = (v[i]-mu)*rs*ln_w[c] + ln_b[c];
  }
  if (tid==0) g_biask[row] = 1e9f*(mask[row]-1.f)*L2E;
}

// ---------------------------------------------------------------------------
// 64x64x(K=384) fp32 tiled GEMM:  out[n][c] = sum_k A[n][k]*B[c][k]
// ---------------------------------------------------------------------------
__device__ __forceinline__ void gemm64(const float* __restrict__ A,
                                       const float* __restrict__ B,
                                       int n0, int c0, float acc[4][4]) {
  __shared__ __align__(16) float As[32][68];
  __shared__ __align__(16) float Bs[32][68];
  int tid = threadIdx.x;
  int tx = tid & 15, ty = tid >> 4;
  for (int kt=0; kt<12; kt++){
    int k0 = kt*32;
    #pragma unroll
    for (int i=0;i<2;i++){
      int f = tid + i*256;
      int r = f>>3, k4 = f&7;
      float4 a = *(const float4*)&A[(n0+r)*CC + k0 + k4*4];
      As[k4*4+0][r]=a.x; As[k4*4+1][r]=a.y; As[k4*4+2][r]=a.z; As[k4*4+3][r]=a.w;
      float4 b = *(const float4*)&B[(c0+r)*CC + k0 + k4*4];
      Bs[k4*4+0][r]=b.x; Bs[k4*4+1][r]=b.y; Bs[k4*4+2][r]=b.z; Bs[k4*4+3][r]=b.w;
    }
    __syncthreads();
    #pragma unroll
    for (int kk=0;kk<32;kk++){
      float4 a = *(const float4*)&As[kk][ty*4];
      float4 b = *(const float4*)&Bs[kk][tx*4];
      float av[4]={a.x,a.y,a.z,a.w}, bv[4]={b.x,b.y,b.z,b.w};
      #pragma unroll
      for (int r=0;r<4;r++)
        #pragma unroll
        for (int c=0;c<4;c++) acc[r][c] += av[r]*bv[c];
    }
    __syncthreads();
  }
}

// ---------------------------------------------------------------------------
// All four projections in one kernel (blockIdx.z selects q/k/v/g).
// ---------------------------------------------------------------------------
__global__ __launch_bounds__(256) void proj_kernel(
    const float* __restrict__ wq, const float* __restrict__ bq,
    const float* __restrict__ wk, const float* __restrict__ wv,
    const float* __restrict__ wg) {
  int proj = blockIdx.z;
  const float* W = (proj==0)?wq:(proj==1)?wk:(proj==2)?wv:wg;
  int c0 = blockIdx.x*64, n0 = blockIdx.y*64;
  float acc[4][4] = {};
  gemm64(g_xn, W, n0, c0, acc);
  int tx = threadIdx.x & 15, ty = threadIdx.x >> 4;
  #pragma unroll
  for (int r=0;r<4;r++){
    int row = n0 + ty*4 + r;
    #pragma unroll
    for (int c=0;c<4;c++){
      int col = c0 + tx*4 + c;
      float val = acc[r][c];
      if (proj==0){
        val = (val + bq[col]) * (0.2041241452f * L2E);   // D^-0.5 * log2e
        g_q[(col/DD)*NN*DD + row*DD + (col%DD)] = val;
      } else if (proj==1){
        g_k[(col/DD)*NN*DD + row*DD + (col%DD)] = val;
      } else if (proj==2){
        g_v[(col/DD)*NN*DD + row*DD + (col%DD)] = val;
      } else {
        g_gate[row*CC+col] = 1.f/(1.f+__expf(-val));
      }
    }
  }
}

// ---------------------------------------------------------------------------
// Tensor-core flash attention per (head, 64-query tile), tf32 mma.sync.
// 4 warps x 16 query rows.  Streams 64-key tiles:
//   C := pair*log2e + bias  (fp32, exact)
//   C += Q.K^T via m16n8k8 tf32 (Q pre-scaled by D^-0.5*log2e)
//   online softmax in log2 domain (exp2f = 1 MUFU)
//   P -> smem -> A-frags, O += P.V via m16n8k8 tf32
// Epilogue fuses 1/l and sigmoid-gate multiply.
// ---------------------------------------------------------------------------
__global__ __launch_bounds__(128) void attn_kernel(const float* __restrict__ pair) {
  int h = blockIdx.y, q0 = blockIdx.x*64;
  __shared__ float kT[24][72];     // K^T: banks 8*tg+g -> conflict-free
  __shared__ float v_s[64][24];    // banks 24*tg+g -> conflict-free
  __shared__ float s_s[64][68];    // pair/P: A-frag banks 4g+tg -> conflict-free
  int tid = threadIdx.x;
  int w = tid>>5, lane = tid&31;
  int g = lane>>2, tg = lane&3;
  int r0 = 16*w + g, r1 = r0 + 8;  // this thread's two local rows

  // Q A-frags, kept in registers all kernel (tf32)
  unsigned qa[3][4];
  {
    const float* qb = &g_q[(size_t)h*NN*DD + (size_t)q0*DD];
    #pragma unroll
    for (int j=0;j<3;j++){
      qa[j][0] = cvt_tf32(qb[r0*DD + 8*j+tg]);
      qa[j][1] = cvt_tf32(qb[r1*DD + 8*j+tg]);
      qa[j][2] = cvt_tf32(qb[r0*DD + 8*j+tg+4]);
      qa[j][3] = cvt_tf32(qb[r1*DD + 8*j+tg+4]);
    }
  }
  float m0=-1e30f, m1=-1e30f, l0=0.f, l1=0.f;
  float o[3][4] = {};

  const float* pb = pair + (size_t)h*NN*NN + (size_t)q0*NN;
  const float* kb = g_k + (size_t)h*NN*DD;
  const float* vb = g_v + (size_t)h*NN*DD;

  for (int t=0;t<32;t++){
    int k0 = t*64;
    // stage K^T (transposed) and V
    for (int i=tid; i<1536; i+=128){
      int r = i/24, d = i - r*24;
      kT[d][r]  = kb[(k0+r)*DD + d];
      v_s[r][d] = vb[(k0+r)*DD + d];
    }
    // stage pair*log2e + bias (1024 float4)
    for (int i=tid; i<1024; i+=128){
      int r = i>>4, c4 = (i&15)*4;
      float4 p4 = *(const float4*)&pb[(size_t)r*NN + k0 + c4];
      float4 b4 = *(const float4*)&g_biask[k0+c4];
      s_s[r][c4+0] = fmaf(p4.x, L2E, b4.x);
      s_s[r][c4+1] = fmaf(p4.y, L2E, b4.y);
      s_s[r][c4+2] = fmaf(p4.z, L2E, b4.z);
      s_s[r][c4+3] = fmaf(p4.w, L2E, b4.w);
    }
    __syncthreads();

    // C init from pair+bias (fp32 exact)
    float c[8][4];
    #pragma unroll
    for (int nn=0;nn<8;nn++){
      float2 x0 = *(const float2*)&s_s[r0][8*nn+2*tg];
      float2 x1 = *(const float2*)&s_s[r1][8*nn+2*tg];
      c[nn][0]=x0.x; c[nn][1]=x0.y; c[nn][2]=x1.x; c[nn][3]=x1.y;
    }
    // S += Q.K^T
    #pragma unroll
    for (int j=0;j<3;j++){
      #pragma unroll
      for (int nn=0;nn<8;nn++){
        unsigned b0 = cvt_tf32(kT[8*j+tg  ][8*nn+g]);
        unsigned b1 = cvt_tf32(kT[8*j+tg+4][8*nn+g]);
        mma_tf32(c[nn], qa[j], b0, b1);
      }
    }

    // online softmax (log2 domain)
    float rm0=-1e30f, rm1=-1e30f;
    #pragma unroll
    for (int nn=0;nn<8;nn++){
      rm0 = fmaxf(rm0, fmaxf(c[nn][0], c[nn][1]));
      rm1 = fmaxf(rm1, fmaxf(c[nn][2], c[nn][3]));
    }
    rm0 = fmaxf(rm0, __shfl_xor_sync(~0u,rm0,1));
    rm0 = fmaxf(rm0, __shfl_xor_sync(~0u,rm0,2));
    rm1 = fmaxf(rm1, __shfl_xor_sync(~0u,rm1,1));
    rm1 = fmaxf(rm1, __shfl_xor_sync(~0u,rm1,2));
    float mn0 = fmaxf(m0, rm0), mn1 = fmaxf(m1, rm1);
    float a0 = exp2f(m0-mn0), a1 = exp2f(m1-mn1);
    float ls0=0.f, ls1=0.f;
    #pragma unroll
    for (int nn=0;nn<8;nn++){
      float p00 = exp2f(c[nn][0]-mn0);
      float p01 = exp2f(c[nn][1]-mn0);
      float p10 = exp2f(c[nn][2]-mn1);
      float p11 = exp2f(c[nn][3]-mn1);
      ls0 += p00+p01; ls1 += p10+p11;
      *(float2*)&s_s[r0][8*nn+2*tg] = make_float2(p00,p01);
      *(float2*)&s_s[r1][8*nn+2*tg] = make_float2(p10,p11);
    }
    ls0 += __shfl_xor_sync(~0u,ls0,1); ls0 += __shfl_xor_sync(~0u,ls0,2);
    ls1 += __shfl_xor_sync(~0u,ls1,1); ls1 += __shfl_xor_sync(~0u,ls1,2);
    l0 = l0*a0 + ls0; l1 = l1*a1 + ls1; m0 = mn0; m1 = mn1;
    #pragma unroll
    for (int nn=0;nn<3;nn++){
      o[nn][0]*=a0; o[nn][1]*=a0; o[nn][2]*=a1; o[nn][3]*=a1;
    }
    __syncwarp();   // P rows are warp-private; order STS before LDS

    // O += P.V
    #pragma unroll
    for (int j=0;j<8;j++){
      unsigned a[4];
      a[0] = cvt_tf32(s_s[r0][8*j+tg]);
      a[1] = cvt_tf32(s_s[r1][8*j+tg]);
      a[2] = cvt_tf32(s_s[r0][8*j+tg+4]);
      a[3] = cvt_tf32(s_s[r1][8*j+tg+4]);
      #pragma unroll
      for (int nn=0;nn<3;nn++){
        unsigned b0 = cvt_tf32(v_s[8*j+tg  ][8*nn+g]);
        unsigned b1 = cvt_tf32(v_s[8*j+tg+4][8*nn+g]);
        mma_tf32(o[nn], a, b0, b1);
      }
    }
    __syncthreads();  // before next tile overwrites smem
  }

  // epilogue: normalize + gate
  float il0 = 1.f/l0, il1 = 1.f/l1;
  int n0g = q0 + r0, n1g = q0 + r1;
  #pragma unroll
  for (int nn=0;nn<3;nn++){
    int col = h*DD + 8*nn + 2*tg;
    float2 gt0 = *(const float2*)&g_gate[n0g*CC + col];
    float2 gt1 = *(const float2*)&g_gate[n1g*CC + col];
    float2 y0 = make_float2(o[nn][0]*il0*gt0.x, o[nn][1]*il0*gt0.y);
    float2 y1 = make_float2(o[nn][2]*il1*gt1.x, o[nn][3]*il1*gt1.y);
    *(float2*)&g_gated[n0g*CC+col] = y0;
    *(float2*)&g_gated[n1g*CC+col] = y1;
  }
}

// ---------------------------------------------------------------------------
// Output projection: out = gated @ wo.T
// ---------------------------------------------------------------------------
__global__ __launch_bounds__(256) void out_kernel(const float* __restrict__ wo,
                                                  float* __restrict__ out) {
  int c0 = blockIdx.x*64, n0 = blockIdx.y*64;
  float acc[4][4] = {};
  gemm64(g_gated, wo, n0, c0, acc);
  int tx = threadIdx.x & 15, ty = threadIdx.x >> 4;
  #pragma unroll
  for (int r=0;r<4;r++)
    #pragma unroll
    for (int c=0;c<4;c++)
      out[(n0+ty*4+r)*CC + c0+tx*4+c] = acc[r][c];
}

// ---------------------------------------------------------------------------
extern "C" void kernel_launch(void* const* d_in, const int* in_sizes, int n_in,
                              void* d_out, int out_size) {
  const float* x    = (const float*)d_in[0];
  const float* mask = (const float*)d_in[1];
  const float* pair = (const float*)d_in[2];
  const float* ln_w = (const float*)d_in[3];
  const float* ln_b = (const float*)d_in[4];
  const float* wq   = (const float*)d_in[5];
  const float* bq   = (const float*)d_in[6];
  const float* wk   = (const float*)d_in[7];
  const float* wv   = (const float*)d_in[8];
  const float* wg   = (const float*)d_in[9];
  const float* wo   = (const float*)d_in[10];
  float* out = (float*)d_out;

  ln_kernel<<<NN,128>>>(x,mask,ln_w,ln_b);
  proj_kernel<<<dim3(6,32,4),256>>>(wq,bq,wk,wv,wg);
  attn_kernel<<<dim3(32,16),128>>>(pair);
  out_kernel<<<dim3(6,32),256>>>(wo,out);
}

// round 4
// speedup vs baseline: 2.6347x; 1.0188x over previous
#include <cuda_runtime.h>
#include <math.h>

#define NN 2048
#define CC 384
#define HH 16
#define DD 24
#define L2E 1.44269504088896340736f

// Scratch (allocation-free rule: __device__ globals)
__device__ float g_xn[NN*CC];
__device__ float g_q[NN*CC];      // [H][N][D], pre-scaled by D^-0.5 * log2e
__device__ float g_k[NN*CC];      // [H][N][D]
__device__ float g_v[NN*CC];      // [H][N][D]
__device__ float g_gate[NN*CC];   // sigmoid(xn @ wg.T), [N][C]
__device__ float g_gated[NN*CC];  // wa * gate, [N][C]
__device__ float g_biask[NN];     // 1e9*(mask-1)*log2e

// ---------------------------------------------------------------------------
__device__ __forceinline__ unsigned cvt_tf32(float x){
  unsigned r; asm("cvt.rna.tf32.f32 %0, %1;" : "=r"(r) : "f"(x)); return r;
}
__device__ __forceinline__ void mma_tf32(float c[4], const unsigned a[4],
                                         unsigned b0, unsigned b1){
  asm volatile("mma.sync.aligned.m16n8k8.row.col.f32.tf32.tf32.f32 "
    "{%0,%1,%2,%3}, {%4,%5,%6,%7}, {%8,%9}, {%0,%1,%2,%3};"
    : "+f"(c[0]),"+f"(c[1]),"+f"(c[2]),"+f"(c[3])
    : "r"(a[0]),"r"(a[1]),"r"(a[2]),"r"(a[3]), "r"(b0),"r"(b1));
}

// ---------------------------------------------------------------------------
// LayerNorm over C=384 per row; also precompute additive key bias (log2 dom).
// ---------------------------------------------------------------------------
__global__ __launch_bounds__(128) void ln_kernel(
    const float* __restrict__ x, const float* __restrict__ mask,
    const float* __restrict__ ln_w, const float* __restrict__ ln_b) {
  int row = blockIdx.x, tid = threadIdx.x;
  const float* xr = x + row*CC;
  float v[3]; float s = 0.f;
  #pragma unroll
  for (int i=0;i<3;i++){ v[i]=xr[tid+128*i]; s+=v[i]; }
  __shared__ float red[4];
  #pragma unroll
  for (int o=16;o;o>>=1) s += __shfl_xor_sync(~0u,s,o);
  if ((tid&31)==0) red[tid>>5]=s;
  __syncthreads();
  float mu = (red[0]+red[1]+red[2]+red[3])*(1.f/CC);
  __syncthreads();
  float sq=0.f;
  #pragma unroll
  for (int i=0;i<3;i++){ float d=v[i]-mu; sq+=d*d; }
  #pragma unroll
  for (int o=16;o;o>>=1) sq += __shfl_xor_sync(~0u,sq,o);
  if ((tid&31)==0) red[tid>>5]=sq;
  __syncthreads();
  float var = (red[0]+red[1]+red[2]+red[3])*(1.f/CC);
  float rs = rsqrtf(var + 1e-5f);
  #pragma unroll
  for (int i=0;i<3;i++){
    int c = tid+128*i;
    g_xn[row*CC+c] = (v[i]-mu)*rs*ln_w[c] + ln_b[c];
  }
  if (tid==0) g_biask[row] = 1e9f*(mask[row]-1.f)*L2E;
}

// ---------------------------------------------------------------------------
// 3xTF32 tensor-core GEMM, 64x64 tile, K=384:  out[n][c]=sum_k A[n][k]*B[c][k]
// 256 threads = 8 warps: warp (wm=w>>1, wn=w&1) owns rows wm*16.., cols wn*32..
// D = Ah*Bh + Al*Bh + Ah*Bl  (error ~2^-22, preserves fp32-grade accuracy)
// smem stride 36 -> frag-load banks 4g+tg, conflict-free.
// acc[4][4]: nn-th n8 tile; rows (g, g+8), cols (8nn+2tg, +1) within warp tile.
// ---------------------------------------------------------------------------
__device__ __forceinline__ void gemm_tc(const float* __restrict__ A,
                                        const float* __restrict__ B,
                                        int n0, int c0, float acc[4][4]) {
  __shared__ unsigned Ah[64][36], Al[64][36], Bh[64][36], Bl[64][36];
  int tid = threadIdx.x;
  int lane = tid&31, w = tid>>5;
  int wm = w>>1, wn = w&1;
  int g = lane>>2, tg = lane&3;
  int r0 = wm*16 + g, r1 = r0 + 8;

  for (int kt=0; kt<12; kt++){
    int k0 = kt*32;
    #pragma unroll
    for (int i=0;i<2;i++){
      int f = tid + i*256;          // 0..511 float4 slots
      int r = f>>3, c4 = (f&7)*4;
      float4 a = *(const float4*)&A[(n0+r)*CC + k0 + c4];
      float4 b = *(const float4*)&B[(c0+r)*CC + k0 + c4];
      float av[4]={a.x,a.y,a.z,a.w}, bv[4]={b.x,b.y,b.z,b.w};
      #pragma unroll
      for (int j=0;j<4;j++){
        unsigned h = cvt_tf32(av[j]);
        Ah[r][c4+j] = h;
        Al[r][c4+j] = cvt_tf32(av[j] - __uint_as_float(h));
        unsigned hb = cvt_tf32(bv[j]);
        Bh[r][c4+j] = hb;
        Bl[r][c4+j] = cvt_tf32(bv[j] - __uint_as_float(hb));
      }
    }
    __syncthreads();
    #pragma unroll
    for (int ks=0;ks<4;ks++){
      int k = ks*8;
      unsigned ah[4], al[4];
      ah[0]=Ah[r0][k+tg]; ah[1]=Ah[r1][k+tg]; ah[2]=Ah[r0][k+tg+4]; ah[3]=Ah[r1][k+tg+4];
      al[0]=Al[r0][k+tg]; al[1]=Al[r1][k+tg]; al[2]=Al[r0][k+tg+4]; al[3]=Al[r1][k+tg+4];
      #pragma unroll
      for (int nn=0;nn<4;nn++){
        int col = wn*32 + 8*nn + g;
        unsigned bh0=Bh[col][k+tg], bh1=Bh[col][k+tg+4];
        unsigned bl0=Bl[col][k+tg], bl1=Bl[col][k+tg+4];
        mma_tf32(acc[nn], ah, bh0, bh1);
        mma_tf32(acc[nn], al, bh0, bh1);
        mma_tf32(acc[nn], ah, bl0, bl1);
      }
    }
    __syncthreads();
  }
}

// ---------------------------------------------------------------------------
// All four projections in one kernel (blockIdx.z selects q/k/v/g).
// ---------------------------------------------------------------------------
__device__ __forceinline__ void proj_store(int proj, int row, int col, float val,
                                           const float* __restrict__ bq){
  if (proj==0){
    val = (val + bq[col]) * (0.2041241452f * L2E);   // D^-0.5 * log2e
    g_q[(col/DD)*NN*DD + row*DD + (col%DD)] = val;
  } else if (proj==1){
    g_k[(col/DD)*NN*DD + row*DD + (col%DD)] = val;
  } else if (proj==2){
    g_v[(col/DD)*NN*DD + row*DD + (col%DD)] = val;
  } else {
    g_gate[row*CC+col] = 1.f/(1.f+__expf(-val));
  }
}

__global__ __launch_bounds__(256) void proj_kernel(
    const float* __restrict__ wq, const float* __restrict__ bq,
    const float* __restrict__ wk, const float* __restrict__ wv,
    const float* __restrict__ wg) {
  int proj = blockIdx.z;
  const float* W = (proj==0)?wq:(proj==1)?wk:(proj==2)?wv:wg;
  int c0 = blockIdx.x*64, n0 = blockIdx.y*64;
  float acc[4][4] = {};
  gemm_tc(g_xn, W, n0, c0, acc);
  int lane = threadIdx.x&31, w = threadIdx.x>>5;
  int wm = w>>1, wn = w&1;
  int g = lane>>2, tg = lane&3;
  int row0 = n0 + wm*16 + g, row1 = row0 + 8;
  #pragma unroll
  for (int nn=0;nn<4;nn++){
    int col = c0 + wn*32 + 8*nn + 2*tg;
    proj_store(proj, row0, col,   acc[nn][0], bq);
    proj_store(proj, row0, col+1, acc[nn][1], bq);
    proj_store(proj, row1, col,   acc[nn][2], bq);
    proj_store(proj, row1, col+1, acc[nn][3], bq);
  }
}

// ---------------------------------------------------------------------------
// Tensor-core flash attention per (head, 64-query tile), tf32 mma.sync.
// ---------------------------------------------------------------------------
__global__ __launch_bounds__(128) void attn_kernel(const float* __restrict__ pair) {
  int h = blockIdx.y, q0 = blockIdx.x*64;
  __shared__ float kT[24][72];     // K^T: banks 8*tg+g -> conflict-free
  __shared__ float v_s[64][24];    // banks 24*tg+g -> conflict-free
  __shared__ float s_s[64][68];    // pair/P: A-frag banks 4g+tg -> conflict-free
  int tid = threadIdx.x;
  int w = tid>>5, lane = tid&31;
  int g = lane>>2, tg = lane&3;
  int r0 = 16*w + g, r1 = r0 + 8;  // this thread's two local rows

  // Q A-frags, kept in registers all kernel (tf32)
  unsigned qa[3][4];
  {
    const float* qb = &g_q[(size_t)h*NN*DD + (size_t)q0*DD];
    #pragma unroll
    for (int j=0;j<3;j++){
      qa[j][0] = cvt_tf32(qb[r0*DD + 8*j+tg]);
      qa[j][1] = cvt_tf32(qb[r1*DD + 8*j+tg]);
      qa[j][2] = cvt_tf32(qb[r0*DD + 8*j+tg+4]);
      qa[j][3] = cvt_tf32(qb[r1*DD + 8*j+tg+4]);
    }
  }
  float m0=-1e30f, m1=-1e30f, l0=0.f, l1=0.f;
  float o[3][4] = {};

  const float* pb = pair + (size_t)h*NN*NN + (size_t)q0*NN;
  const float* kb = g_k + (size_t)h*NN*DD;
  const float* vb = g_v + (size_t)h*NN*DD;

  for (int t=0;t<32;t++){
    int k0 = t*64;
    // stage K^T (transposed) and V
    for (int i=tid; i<1536; i+=128){
      int r = i/24, d = i - r*24;
      kT[d][r]  = kb[(k0+r)*DD + d];
      v_s[r][d] = vb[(k0+r)*DD + d];
    }
    // stage pair*log2e + bias (1024 float4)
    for (int i=tid; i<1024; i+=128){
      int r = i>>4, c4 = (i&15)*4;
      float4 p4 = *(const float4*)&pb[(size_t)r*NN + k0 + c4];
      float4 b4 = *(const float4*)&g_biask[k0+c4];
      s_s[r][c4+0] = fmaf(p4.x, L2E, b4.x);
      s_s[r][c4+1] = fmaf(p4.y, L2E, b4.y);
      s_s[r][c4+2] = fmaf(p4.z, L2E, b4.z);
      s_s[r][c4+3] = fmaf(p4.w, L2E, b4.w);
    }
    __syncthreads();

    // C init from pair+bias (fp32 exact)
    float c[8][4];
    #pragma unroll
    for (int nn=0;nn<8;nn++){
      float2 x0 = *(const float2*)&s_s[r0][8*nn+2*tg];
      float2 x1 = *(const float2*)&s_s[r1][8*nn+2*tg];
      c[nn][0]=x0.x; c[nn][1]=x0.y; c[nn][2]=x1.x; c[nn][3]=x1.y;
    }
    // S += Q.K^T
    #pragma unroll
    for (int j=0;j<3;j++){
      #pragma unroll
      for (int nn=0;nn<8;nn++){
        unsigned b0 = cvt_tf32(kT[8*j+tg  ][8*nn+g]);
        unsigned b1 = cvt_tf32(kT[8*j+tg+4][8*nn+g]);
        mma_tf32(c[nn], qa[j], b0, b1);
      }
    }

    // online softmax (log2 domain)
    float rm0=-1e30f, rm1=-1e30f;
    #pragma unroll
    for (int nn=0;nn<8;nn++){
      rm0 = fmaxf(rm0, fmaxf(c[nn][0], c[nn][1]));
      rm1 = fmaxf(rm1, fmaxf(c[nn][2], c[nn][3]));
    }
    rm0 = fmaxf(rm0, __shfl_xor_sync(~0u,rm0,1));
    rm0 = fmaxf(rm0, __shfl_xor_sync(~0u,rm0,2));
    rm1 = fmaxf(rm1, __shfl_xor_sync(~0u,rm1,1));
    rm1 = fmaxf(rm1, __shfl_xor_sync(~0u,rm1,2));
    float mn0 = fmaxf(m0, rm0), mn1 = fmaxf(m1, rm1);
    float a0 = exp2f(m0-mn0), a1 = exp2f(m1-mn1);
    float ls0=0.f, ls1=0.f;
    #pragma unroll
    for (int nn=0;nn<8;nn++){
      float p00 = exp2f(c[nn][0]-mn0);
      float p01 = exp2f(c[nn][1]-mn0);
      float p10 = exp2f(c[nn][2]-mn1);
      float p11 = exp2f(c[nn][3]-mn1);
      ls0 += p00+p01; ls1 += p10+p11;
      *(float2*)&s_s[r0][8*nn+2*tg] = make_float2(p00,p01);
      *(float2*)&s_s[r1][8*nn+2*tg] = make_float2(p10,p11);
    }
    ls0 += __shfl_xor_sync(~0u,ls0,1); ls0 += __shfl_xor_sync(~0u,ls0,2);
    ls1 += __shfl_xor_sync(~0u,ls1,1); ls1 += __shfl_xor_sync(~0u,ls1,2);
    l0 = l0*a0 + ls0; l1 = l1*a1 + ls1; m0 = mn0; m1 = mn1;
    #pragma unroll
    for (int nn=0;nn<3;nn++){
      o[nn][0]*=a0; o[nn][1]*=a0; o[nn][2]*=a1; o[nn][3]*=a1;
    }
    __syncwarp();   // P rows are warp-private; order STS before LDS

    // O += P.V
    #pragma unroll
    for (int j=0;j<8;j++){
      unsigned a[4];
      a[0] = cvt_tf32(s_s[r0][8*j+tg]);
      a[1] = cvt_tf32(s_s[r1][8*j+tg]);
      a[2] = cvt_tf32(s_s[r0][8*j+tg+4]);
      a[3] = cvt_tf32(s_s[r1][8*j+tg+4]);
      #pragma unroll
      for (int nn=0;nn<3;nn++){
        unsigned b0 = cvt_tf32(v_s[8*j+tg  ][8*nn+g]);
        unsigned b1 = cvt_tf32(v_s[8*j+tg+4][8*nn+g]);
        mma_tf32(o[nn], a, b0, b1);
      }
    }
    __syncthreads();  // before next tile overwrites smem
  }

  // epilogue: normalize + gate
  float il0 = 1.f/l0, il1 = 1.f/l1;
  int n0g = q0 + r0, n1g = q0 + r1;
  #pragma unroll
  for (int nn=0;nn<3;nn++){
    int col = h*DD + 8*nn + 2*tg;
    float2 gt0 = *(const float2*)&g_gate[n0g*CC + col];
    float2 gt1 = *(const float2*)&g_gate[n1g*CC + col];
    float2 y0 = make_float2(o[nn][0]*il0*gt0.x, o[nn][1]*il0*gt0.y);
    float2 y1 = make_float2(o[nn][2]*il1*gt1.x, o[nn][3]*il1*gt1.y);
    *(float2*)&g_gated[n0g*CC+col] = y0;
    *(float2*)&g_gated[n1g*CC+col] = y1;
  }
}

// ---------------------------------------------------------------------------
// Output projection: out = gated @ wo.T  (3xTF32 tensor-core)
// ---------------------------------------------------------------------------
__global__ __launch_bounds__(256) void out_kernel(const float* __restrict__ wo,
                                                  float* __restrict__ out) {
  int c0 = blockIdx.x*64, n0 = blockIdx.y*64;
  float acc[4][4] = {};
  gemm_tc(g_gated, wo, n0, c0, acc);
  int lane = threadIdx.x&31, w = threadIdx.x>>5;
  int wm = w>>1, wn = w&1;
  int g = lane>>2, tg = lane&3;
  int row0 = n0 + wm*16 + g, row1 = row0 + 8;
  #pragma unroll
  for (int nn=0;nn<4;nn++){
    int col = c0 + wn*32 + 8*nn + 2*tg;
    *(float2*)&out[row0*CC+col] = make_float2(acc[nn][0], acc[nn][1]);
    *(float2*)&out[row1*CC+col] = make_float2(acc[nn][2], acc[nn][3]);
  }
}

// ---------------------------------------------------------------------------
extern "C" void kernel_launch(void* const* d_in, const int* in_sizes, int n_in,
                              void* d_out, int out_size) {
  const float* x    = (const float*)d_in[0];
  const float* mask = (const float*)d_in[1];
  const float* pair = (const float*)d_in[2];
  const float* ln_w = (const float*)d_in[3];
  const float* ln_b = (const float*)d_in[4];
  const float* wq   = (const float*)d_in[5];
  const float* bq   = (const float*)d_in[6];
  const float* wk   = (const float*)d_in[7];
  const float* wv   = (const float*)d_in[8];
  const float* wg   = (const float*)d_in[9];
  const float* wo   = (const float*)d_in[10];
  float* out = (float*)d_out;

  ln_kernel<<<NN,128>>>(x,mask,ln_w,ln_b);
  proj_kernel<<<dim3(6,32,4),256>>>(wq,bq,wk,wv,wg);
  attn_kernel<<<dim3(32,16),128>>>(pair);
  out_kernel<<<dim3(6,32),256>>>(wo,out);
}